// round 6
// baseline (speedup 1.0000x reference)
#include <cuda_runtime.h>
#include <cstdint>

#define HD   128
#define TS   512
#define BSZ  4096
#define CD   10
#define BT   32
#define NCTA (BSZ / BT)   // 128
#define NTHR 256          // 8 warps; warp w owns columns 4w..4w+3
#define TPREF 128
#define DELTA 0.3f        // threshold-absorb level, certified at runtime

// ---- shared memory layout (bytes) ----
#define SM_W 0                       // Ws[k][m] plain, row 512B : 64 KB
#define SM_X (64 * 1024)             // xs[32][TPREF]            : 16 KB
#define SM_H (80 * 1024)             // h[32][128] in-place      : 16 KB
#define SM_F (96 * 1024)             // absorb flag, xmax
#define SM_SZ (SM_F + 128)

typedef unsigned long long ull;

static __device__ __forceinline__ uint32_t smem_u32(const void* p) {
    uint32_t a;
    asm("{ .reg .u64 t; cvta.to.shared.u64 t, %1; cvt.u32.u64 %0, t; }" : "=r"(a) : "l"(p));
    return a;
}
static __device__ __forceinline__ ull pk(float lo, float hi) {
    ull r; asm("mov.b64 %0, {%1, %2};" : "=l"(r) : "f"(lo), "f"(hi)); return r;
}
static __device__ __forceinline__ void upk(ull v, float& lo, float& hi) {
    asm("mov.b64 {%0, %1}, %2;" : "=f"(lo), "=f"(hi) : "l"(v));
}
static __device__ __forceinline__ ull fma2(ull a, ull b, ull c) {
    ull d; asm("fma.rn.f32x2 %0, %1, %2, %3;" : "=l"(d) : "l"(a), "l"(b), "l"(c)); return d;
}
static __device__ __forceinline__ ull add2(ull a, ull b) {
    ull d; asm("add.rn.f32x2 %0, %1, %2;" : "=l"(d) : "l"(a), "l"(b)); return d;
}
// exactly +-1.0f for |x| >~ 9 (matches fp32 tanhf saturation); ~1e-7 abs err
static __device__ __forceinline__ float tanh_acc(float v) {
    float a = fabsf(v);
    float e = __expf(2.0f * a);
    float r = 1.0f - 2.0f / (e + 1.0f);
    return copysignf(r, v);
}

// w-quad load: two f32x2 (m0,m1),(m2,m3) in one conflict-free LDS.128
#define WLOAD(w01, w23, base, IMM) \
    asm volatile("ld.shared.v2.b64 {%0,%1}, [%2+" IMM "];" \
                 : "=l"(w01), "=l"(w23) : "r"(base))

// epilogue: tanh, in-place float4 write, threshold votes.
// am bits: j -> all h >= DELTA; 8+j -> all h <= -DELTA (uniform across warp)
template <int J>
static __device__ __forceinline__ unsigned
epilogue(const ull* a01, const ull* a23, float* Hs, const int* cols, int mb)
{
    unsigned am = 0;
    #pragma unroll
    for (int j = 0; j < J; ++j) {
        float v0, v1, v2, v3;
        upk(a01[j], v0, v1); upk(a23[j], v2, v3);
        v0 = tanh_acc(v0); v1 = tanh_acc(v1);
        v2 = tanh_acc(v2); v3 = tanh_acc(v3);
        *(float4*)(Hs + cols[j] * HD + mb) = make_float4(v0, v1, v2, v3);
        bool p = (v0 >=  DELTA) & (v1 >=  DELTA) & (v2 >=  DELTA) & (v3 >=  DELTA);
        bool n = (v0 <= -DELTA) & (v1 <= -DELTA) & (v2 <= -DELTA) & (v3 <= -DELTA);
        unsigned bp_ = __ballot_sync(0xffffffffu, p);
        unsigned bn_ = __ballot_sync(0xffffffffu, n);
        if (bp_ == 0xffffffffu) am |= 1u << j;
        if (bn_ == 0xffffffffu) am |= 1u << (8 + j);
    }
    return am;
}

// one recurrence step for J live columns; warp covers m = 4*lane..4*lane+3.
// For J<=2, accumulators split into even/odd-k4 chains (halved tail latency).
template <int J>
static __device__ __forceinline__ unsigned
do_step(uint32_t wbase, float* Hs, const int* cols, const float* xv,
        ull wx01, ull wx23, ull bh01, ull bh23, int mb)
{
    constexpr int CH = (J <= 2) ? 2 : 1;
    ull a01[J][CH], a23[J][CH];
    #pragma unroll
    for (int j = 0; j < J; ++j) {
        ull xp = pk(xv[j], xv[j]);
        a01[j][0] = fma2(wx01, xp, bh01);
        a23[j][0] = fma2(wx23, xp, bh23);
        if (CH == 2) { a01[j][CH - 1] = 0ull; a23[j][CH - 1] = 0ull; }
    }
    #pragma unroll 4
    for (int k4 = 0; k4 < 32; ++k4) {
        const int ch = (CH == 2) ? (k4 & 1) : 0;
        float4 hv[J];
        #pragma unroll
        for (int j = 0; j < J; ++j)                       // broadcast LDS.128
            hv[j] = *(const float4*)(Hs + cols[j] * HD + 4 * k4);
        const uint32_t wb = wbase + (uint32_t)k4 * 2048u;
        ull w01, w23;
        WLOAD(w01, w23, wb, "0");
        #pragma unroll
        for (int j = 0; j < J; ++j) {
            ull rp = pk(hv[j].x, hv[j].x);
            a01[j][ch] = fma2(w01, rp, a01[j][ch]);
            a23[j][ch] = fma2(w23, rp, a23[j][ch]);
        }
        WLOAD(w01, w23, wb, "512");
        #pragma unroll
        for (int j = 0; j < J; ++j) {
            ull rp = pk(hv[j].y, hv[j].y);
            a01[j][ch] = fma2(w01, rp, a01[j][ch]);
            a23[j][ch] = fma2(w23, rp, a23[j][ch]);
        }
        WLOAD(w01, w23, wb, "1024");
        #pragma unroll
        for (int j = 0; j < J; ++j) {
            ull rp = pk(hv[j].z, hv[j].z);
            a01[j][ch] = fma2(w01, rp, a01[j][ch]);
            a23[j][ch] = fma2(w23, rp, a23[j][ch]);
        }
        WLOAD(w01, w23, wb, "1536");
        #pragma unroll
        for (int j = 0; j < J; ++j) {
            ull rp = pk(hv[j].w, hv[j].w);
            a01[j][ch] = fma2(w01, rp, a01[j][ch]);
            a23[j][ch] = fma2(w23, rp, a23[j][ch]);
        }
    }
    ull f01[J], f23[J];
    #pragma unroll
    for (int j = 0; j < J; ++j) {
        f01[j] = (CH == 2) ? add2(a01[j][0], a01[j][CH - 1]) : a01[j][0];
        f23[j] = (CH == 2) ? add2(a23[j][0], a23[j][CH - 1]) : a23[j][0];
    }
    return epilogue<J>(f01, f23, Hs, cols, mb);
}

__global__ void __launch_bounds__(NTHR, 1)
rnn_kernel(const float* __restrict__ x,   const float* __restrict__ Whx,
           const float* __restrict__ Whh, const float* __restrict__ Wph,
           const float* __restrict__ bh,  const float* __restrict__ bp,
           float* __restrict__ out)
{
    extern __shared__ char sm[];
    float* Xs = (float*)(sm + SM_X);
    float* Hs = (float*)(sm + SM_H);
    int*      absorb = (int*)(sm + SM_F);
    unsigned* xmaxb  = (unsigned*)(sm + SM_F + 4);

    const int tid  = threadIdx.x;
    const int lane = tid & 31;
    const int wid  = tid >> 5;           // owns cols 4*wid..4*wid+3
    const int mb   = 4 * lane;           // m-quad
    const int b0   = blockIdx.x * BT;

    if (tid == 0) { *absorb = 1; *xmaxb = 0u; }
    __syncthreads();

    // ---- Whh -> Ws[k][m] (float4 LDG over k; conflict-free scalar STS) ----
    {
        bool nonneg = true;
        for (int i = tid; i < HD * HD / 4; i += NTHR) {
            int m = i & 127, kq = i >> 7;
            float4 v = *(const float4*)(Whh + (size_t)m * HD + 4 * kq);
            nonneg &= (v.x >= 0.f) & (v.y >= 0.f) & (v.z >= 0.f) & (v.w >= 0.f);
            float vv[4] = {v.x, v.y, v.z, v.w};
            #pragma unroll
            for (int q = 0; q < 4; ++q)
                *(float*)(sm + SM_W + (4 * kq + q) * 512 + m * 4) = vv[q];
        }
        if (!nonneg) atomicAnd(absorb, 0);   // positivity required by threshold cert
    }
    // ---- x: streaming max over all t; store t < TPREF ----
    {
        float lm = 0.0f;
        for (int i = tid; i < BT * TS / 4; i += NTHR) {
            int b = i >> 7, tq = i & 127;
            float4 v = *(const float4*)(x + (size_t)(b0 + b) * TS + 4 * tq);
            lm = fmaxf(lm, fmaxf(fmaxf(fabsf(v.x), fabsf(v.y)),
                                 fmaxf(fabsf(v.z), fabsf(v.w))));
            if (tq < TPREF / 4)
                *(float4*)(Xs + b * TPREF + 4 * tq) = v;
        }
        atomicMax(xmaxb, __float_as_uint(lm));   // |x| bits order-preserving
    }
    __syncthreads();

    // ---- certificate: min_m(rowsum_m*DELTA - |Whx_m|*Xmax - |bh_m|) > 10 ----
    if (tid < HD) {
        int m = tid;
        float s0 = 0.f, s1 = 0.f, s2 = 0.f, s3 = 0.f;
        for (int k = 0; k < HD; k += 4) {
            s0 += *(const float*)(sm + SM_W + (k    ) * 512 + m * 4);
            s1 += *(const float*)(sm + SM_W + (k + 1) * 512 + m * 4);
            s2 += *(const float*)(sm + SM_W + (k + 2) * 512 + m * 4);
            s3 += *(const float*)(sm + SM_W + (k + 3) * 512 + m * 4);
        }
        float rs = (s0 + s1) + (s2 + s3);
        float bound = rs * DELTA - fabsf(Whx[m]) * __uint_as_float(*xmaxb) - fabsf(bh[m]);
        if (!(bound > 10.0f)) atomicAnd(absorb, 0);
    }
    __syncthreads();
    const bool absorb_ok = (*absorb != 0);

    const float4 wxv = *(const float4*)(Whx + mb);
    const float4 bhv = *(const float4*)(bh  + mb);
    const ull wx01 = pk(wxv.x, wxv.y), wx23 = pk(wxv.z, wxv.w);
    const ull bh01 = pk(bhv.x, bhv.y), bh23 = pk(bhv.z, bhv.w);
    const uint32_t wbase = smem_u32(sm) + SM_W + (uint32_t)lane * 16u;

    // ================= barrier-free per-warp recurrence (in-place h) =================
    int cols[4] = {4 * wid, 4 * wid + 1, 4 * wid + 2, 4 * wid + 3};
    int nact = 4;

    for (int t = 0; t < TS && nact > 0; ++t) {
        float xv[4] = {0.f, 0.f, 0.f, 0.f};
        #pragma unroll
        for (int j = 0; j < 4; ++j)
            if (j < nact)
                xv[j] = (t < TPREF) ? Xs[cols[j] * TPREF + t]
                                    : __ldg(x + (size_t)(b0 + cols[j]) * TS + t);
        unsigned am;
        if (t == 0) {
            // h0 = 0: h1 = tanh(Whx*x0 + bh), no GEMV
            ull a01[4], a23[4];
            #pragma unroll
            for (int j = 0; j < 4; ++j) {
                ull xp = pk(xv[j], xv[j]);
                a01[j] = fma2(wx01, xp, bh01);
                a23[j] = fma2(wx23, xp, bh23);
            }
            am = epilogue<4>(a01, a23, Hs, cols, mb);
        } else switch (nact) {
            case 4: am = do_step<4>(wbase, Hs, cols, xv, wx01, wx23, bh01, bh23, mb); break;
            case 3: am = do_step<3>(wbase, Hs, cols, xv, wx01, wx23, bh01, bh23, mb); break;
            case 2: am = do_step<2>(wbase, Hs, cols, xv, wx01, wx23, bh01, bh23, mb); break;
            default: am = do_step<1>(wbase, Hs, cols, xv, wx01, wx23, bh01, bh23, mb); break;
        }

        // threshold absorption: uniform |h| >= DELTA => next state is exactly
        // uniform +-1 and absorbing (certified). Needs a true step remaining.
        if (absorb_ok && am && t < TS - 1) {
            unsigned amp = am & 0xFFu, amn = am >> 8;
            int nn = 0, nc[4];
            #pragma unroll
            for (int j = 0; j < 4; ++j) {
                if (j >= nact) continue;
                bool ap = (amp >> j) & 1u, an = (amn >> j) & 1u;
                if (ap | an) {
                    float s = ap ? 1.0f : -1.0f;
                    *(float4*)(Hs + cols[j] * HD + mb) = make_float4(s, s, s, s);
                } else nc[nn++] = cols[j];
            }
            nact = nn;
            #pragma unroll
            for (int j = 0; j < 4; ++j) cols[j] = (j < nn) ? nc[j] : 0;
        }
    }

    // ================= projection: warp's own 4 columns =================
    #pragma unroll
    for (int j = 0; j < 4; ++j) {
        int c = 4 * wid + j;
        const float4 hq = *(const float4*)(Hs + c * HD + mb);
        #pragma unroll
        for (int cls = 0; cls < CD; ++cls) {
            const float4 wq = __ldg((const float4*)(Wph + cls * HD) + lane);
            float s = hq.x * wq.x + hq.y * wq.y + hq.z * wq.z + hq.w * wq.w;
            #pragma unroll
            for (int o = 16; o > 0; o >>= 1)
                s += __shfl_xor_sync(0xffffffffu, s, o);
            if (lane == 0)
                out[(size_t)(b0 + c) * CD + cls] = s + __ldg(bp + cls);
        }
    }
}

extern "C" void kernel_launch(void* const* d_in, const int* in_sizes, int n_in,
                              void* d_out, int out_size) {
    const float* x   = (const float*)d_in[0];
    const float* Whx = (const float*)d_in[1];
    const float* Whh = (const float*)d_in[2];
    const float* Wph = (const float*)d_in[3];
    const float* bh  = (const float*)d_in[4];
    const float* bp  = (const float*)d_in[5];
    cudaFuncSetAttribute(rnn_kernel, cudaFuncAttributeMaxDynamicSharedMemorySize, SM_SZ);
    rnn_kernel<<<NCTA, NTHR, SM_SZ>>>(x, Whx, Whh, Wph, bh, bp, (float*)d_out);
}

// round 7
// speedup vs baseline: 1.1716x; 1.1716x over previous
#include <cuda_runtime.h>
#include <cstdint>

#define HD   128
#define TS   512
#define BSZ  4096
#define CD   10
#define BT   32
#define NCTA (BSZ / BT)   // 128
#define NTHR 512          // 16 warps = 8 pairs; pair p owns cols 4p..4p+3
#define TPREF 128

// ---- shared memory layout (bytes) ----
#define SM_W    0                    // Ws[k][m], row 512B        : 64 KB
#define SM_X    (64 * 1024)          // xs[32][TPREF]             : 16 KB
#define SM_H    (80 * 1024)          // h[2][32][128] ping-pong   : 32 KB
#define SM_PART (112 * 1024)         // rowsum partials [4][128]  : 2 KB
#define SM_F    (114 * 1024)         // sflag[32], deltabits, xmax, okpos
#define SM_SZ   (SM_F + 256)

typedef unsigned long long ull;

static __device__ __forceinline__ uint32_t smem_u32(const void* p) {
    uint32_t a;
    asm("{ .reg .u64 t; cvta.to.shared.u64 t, %1; cvt.u32.u64 %0, t; }" : "=r"(a) : "l"(p));
    return a;
}
static __device__ __forceinline__ ull pk(float lo, float hi) {
    ull r; asm("mov.b64 %0, {%1, %2};" : "=l"(r) : "f"(lo), "f"(hi)); return r;
}
static __device__ __forceinline__ void upk(ull v, float& lo, float& hi) {
    asm("mov.b64 {%0, %1}, %2;" : "=f"(lo), "=f"(hi) : "l"(v));
}
static __device__ __forceinline__ ull fma2(ull a, ull b, ull c) {
    ull d; asm("fma.rn.f32x2 %0, %1, %2, %3;" : "=l"(d) : "l"(a), "l"(b), "l"(c)); return d;
}
static __device__ __forceinline__ ull add2(ull a, ull b) {
    ull d; asm("add.rn.f32x2 %0, %1, %2;" : "=l"(d) : "l"(a), "l"(b)); return d;
}
// exactly +-1.0f for |x| >~ 9 (matches fp32 tanhf saturation); ~1e-7 abs err
static __device__ __forceinline__ float tanh_acc(float v) {
    float a = fabsf(v);
    float e = __expf(2.0f * a);
    float r = 1.0f - 2.0f / (e + 1.0f);
    return copysignf(r, v);
}
// direct b64 W load: {W[m],W[m+1]} at thread's m-pair, immediate k offset
#define WLOAD64(w, base, IMM) \
    asm volatile("ld.shared.b64 %0, [%1+" IMM "];" : "=l"(w) : "r"(base))

// epilogue: tanh, float2 write of this half's m-pair, threshold votes.
// am bits: j -> all v >= thr ; 8+j -> all v <= -thr   (uniform across warp)
template <int J>
static __device__ __forceinline__ unsigned
epilogue(const ull* acc, float* hwr, const int* cols, int mb, float thr)
{
    unsigned am = 0;
    #pragma unroll
    for (int j = 0; j < J; ++j) {
        float v0, v1; upk(acc[j], v0, v1);
        v0 = tanh_acc(v0); v1 = tanh_acc(v1);
        *(float2*)(hwr + cols[j] * HD + mb) = make_float2(v0, v1);
        bool p = (v0 >=  thr) & (v1 >=  thr);
        bool n = (v0 <= -thr) & (v1 <= -thr);
        unsigned bp_ = __ballot_sync(0xffffffffu, p);
        unsigned bn_ = __ballot_sync(0xffffffffu, n);
        if (bp_ == 0xffffffffu) am |= 1u << j;
        if (bn_ == 0xffffffffu) am |= 1u << (8 + j);
    }
    return am;
}

// one step for J live columns; this warp covers m = mb, mb+1 (its half).
// J<=2: accumulators split into even/odd-k4 chains (halved tail latency).
template <int J>
static __device__ __forceinline__ unsigned
do_step(uint32_t wbase, const float* hrd, float* hwr, const int* cols,
        const float* xv, ull wx2, ull bh2, int mb, float thr)
{
    constexpr int CH = (J <= 2) ? 2 : 1;
    ull acc[J][CH];
    #pragma unroll
    for (int j = 0; j < J; ++j) {
        acc[j][0] = fma2(wx2, pk(xv[j], xv[j]), bh2);
        if (CH == 2) acc[j][CH - 1] = 0ull;
    }
    #pragma unroll 4
    for (int k4 = 0; k4 < 32; ++k4) {
        const int ch = (CH == 2) ? (k4 & 1) : 0;
        float4 hv[J];
        #pragma unroll
        for (int j = 0; j < J; ++j)                      // broadcast LDS.128
            hv[j] = *(const float4*)(hrd + cols[j] * HD + 4 * k4);
        const uint32_t wb = wbase + (uint32_t)k4 * 2048u;
        ull w;
        WLOAD64(w, wb, "0");
        #pragma unroll
        for (int j = 0; j < J; ++j) acc[j][ch] = fma2(w, pk(hv[j].x, hv[j].x), acc[j][ch]);
        WLOAD64(w, wb, "512");
        #pragma unroll
        for (int j = 0; j < J; ++j) acc[j][ch] = fma2(w, pk(hv[j].y, hv[j].y), acc[j][ch]);
        WLOAD64(w, wb, "1024");
        #pragma unroll
        for (int j = 0; j < J; ++j) acc[j][ch] = fma2(w, pk(hv[j].z, hv[j].z), acc[j][ch]);
        WLOAD64(w, wb, "1536");
        #pragma unroll
        for (int j = 0; j < J; ++j) acc[j][ch] = fma2(w, pk(hv[j].w, hv[j].w), acc[j][ch]);
    }
    ull fin[J];
    #pragma unroll
    for (int j = 0; j < J; ++j)
        fin[j] = (CH == 2) ? add2(acc[j][0], acc[j][CH - 1]) : acc[j][0];
    return epilogue<J>(fin, hwr, cols, mb, thr);
}

__global__ void __launch_bounds__(NTHR, 1)
rnn_kernel(const float* __restrict__ x,   const float* __restrict__ Whx,
           const float* __restrict__ Whh, const float* __restrict__ Wph,
           const float* __restrict__ bh,  const float* __restrict__ bp,
           float* __restrict__ out)
{
    extern __shared__ char sm[];
    float* Xs   = (float*)(sm + SM_X);
    float* Hb0  = (float*)(sm + SM_H);
    float* Hb1  = Hb0 + BT * HD;
    float* part = (float*)(sm + SM_PART);               // [4][128]
    unsigned* sflag     = (unsigned*)(sm + SM_F);       // [2][8][2]
    unsigned* deltabits = (unsigned*)(sm + SM_F + 128);
    unsigned* xmaxb     = (unsigned*)(sm + SM_F + 132);
    int*      okpos     = (int*)(sm + SM_F + 136);

    const int tid  = threadIdx.x;
    const int lane = tid & 31;
    const int wid  = tid >> 5;
    const int pair = wid >> 1;                 // 0..7: owns cols 4*pair..+3
    const int half = wid & 1;                  // m half
    const int mb   = half * 64 + 2 * lane;     // this thread's m pair
    const int b0   = blockIdx.x * BT;

    if (tid == 0) { *deltabits = 0u; *xmaxb = 0u; *okpos = 1; }
    __syncthreads();

    // ---- Whh -> Ws[k][m]; fold in per-thread rowsum partials + nonneg ----
    {
        const int m = tid & 127, grp = tid >> 7;        // grp 0..3
        float rsum = 0.0f;
        bool nonneg = true;
        #pragma unroll
        for (int it = 0; it < 8; ++it) {
            int i  = tid + it * NTHR;                   // m stays == tid&127
            int kq = i >> 7;
            float4 v = *(const float4*)(Whh + (size_t)m * HD + 4 * kq);
            rsum += (v.x + v.y) + (v.z + v.w);
            nonneg &= (v.x >= 0.f) & (v.y >= 0.f) & (v.z >= 0.f) & (v.w >= 0.f);
            float vv[4] = {v.x, v.y, v.z, v.w};
            #pragma unroll
            for (int q = 0; q < 4; ++q)
                *(float*)(sm + SM_W + (4 * kq + q) * 512 + m * 4) = vv[q];
        }
        part[grp * 128 + m] = rsum;
        if (!nonneg) atomicAnd(okpos, 0);
    }
    // ---- x: streaming max over all t; store t < TPREF ----
    {
        float lm = 0.0f;
        #pragma unroll 2
        for (int i = tid; i < BT * TS / 4; i += NTHR) {
            int b = i >> 7, tq = i & 127;
            float4 v = *(const float4*)(x + (size_t)(b0 + b) * TS + 4 * tq);
            lm = fmaxf(lm, fmaxf(fmaxf(fabsf(v.x), fabsf(v.y)),
                                 fmaxf(fabsf(v.z), fabsf(v.w))));
            if (tq < TPREF / 4)
                *(float4*)(Xs + b * TPREF + 4 * tq) = v;
        }
        atomicMax(xmaxb, __float_as_uint(lm));           // |x| bits order-preserving
    }
    __syncthreads();

    // ---- adaptive certificate: delta* = max_m (10+c_m)/rowsum_m ----
    if (tid < HD) {
        int m = tid;
        float rs = part[m] + part[128 + m] + part[256 + m] + part[384 + m];
        float c  = fabsf(Whx[m]) * __uint_as_float(*xmaxb) + fabsf(bh[m]);
        float ratio = (rs > 0.0f) ? (10.0f + c) / rs : 2.0f;
        atomicMax(deltabits, __float_as_uint(ratio));    // positive floats
    }
    __syncthreads();
    const float dstar    = __uint_as_float(*deltabits);
    const bool  exact_ok = (dstar <= 1.0f);              // delta=1 cert (no W>=0 needed)
    const float thr      = (exact_ok && *okpos) ? fmaxf(dstar, 0.05f) : 1.0f;

    const float2 wxv = *(const float2*)(Whx + mb);
    const float2 bhv = *(const float2*)(bh  + mb);
    const ull wx2 = pk(wxv.x, wxv.y);
    const ull bh2 = pk(bhv.x, bhv.y);
    const uint32_t wbase = smem_u32(sm) + SM_W + (uint32_t)(256 * half + 8 * lane);

    // ================= per-pair recurrence (named-barrier scoped) =================
    int cols[4] = {4 * pair, 4 * pair + 1, 4 * pair + 2, 4 * pair + 3};
    int nact = 4, cur = 0;

    for (int t = 0; t < TS && nact > 0; ++t) {
        const float* hrd = (cur == 0) ? Hb0 : Hb1;
        float*       hwr = (cur == 0) ? Hb1 : Hb0;

        float xv[4] = {0.f, 0.f, 0.f, 0.f};
        #pragma unroll
        for (int j = 0; j < 4; ++j)
            if (j < nact)
                xv[j] = (t < TPREF) ? Xs[cols[j] * TPREF + t]
                                    : __ldg(x + (size_t)(b0 + cols[j]) * TS + t);
        unsigned am;
        if (t == 0) {
            // h0 = 0: h1 = tanh(Whx*x0 + bh), no GEMV
            ull a[4];
            #pragma unroll
            for (int j = 0; j < 4; ++j)
                a[j] = fma2(wx2, pk(xv[j], xv[j]), bh2);
            am = epilogue<4>(a, hwr, cols, mb, thr);
        } else switch (nact) {
            case 4: am = do_step<4>(wbase, hrd, hwr, cols, xv, wx2, bh2, mb, thr); break;
            case 3: am = do_step<3>(wbase, hrd, hwr, cols, xv, wx2, bh2, mb, thr); break;
            case 2: am = do_step<2>(wbase, hrd, hwr, cols, xv, wx2, bh2, mb, thr); break;
            default: am = do_step<1>(wbase, hrd, hwr, cols, xv, wx2, bh2, mb, thr); break;
        }

        if (lane == 0) sflag[(t & 1) * 16 + pair * 2 + half] = am;
        asm volatile("bar.sync %0, 64;" :: "r"(1 + pair) : "memory");
        unsigned f0 = sflag[(t & 1) * 16 + pair * 2 + 0];
        unsigned f1 = sflag[(t & 1) * 16 + pair * 2 + 1];
        cur ^= 1;

        // uniform |h| >= thr across ALL 128 m  =>  next state exactly uniform
        // +-1 and absorbing (certified). Needs a true step remaining (t<TS-1).
        if (exact_ok && t < TS - 1) {
            unsigned amp = f0 & f1 & 0xFu;
            unsigned amn = (f0 >> 8) & (f1 >> 8) & 0xFu;
            unsigned ab  = (amp | amn) & ((1u << nact) - 1u);
            if (ab) {
                // absorbed columns: materialize +-1 in BOTH buffers (own half)
                #pragma unroll
                for (int j = 0; j < 4; ++j)
                    if (j < nact && ((ab >> j) & 1u)) {
                        float s = ((amp >> j) & 1u) ? 1.0f : -1.0f;
                        float2 sv = make_float2(s, s);
                        *(float2*)(Hb0 + cols[j] * HD + mb) = sv;
                        *(float2*)(Hb1 + cols[j] * HD + mb) = sv;
                    }
                int nn = 0, nc[4];
                #pragma unroll
                for (int j = 0; j < 4; ++j)
                    if (j < nact && !((ab >> j) & 1u)) nc[nn++] = cols[j];
                nact = nn;
                #pragma unroll
                for (int j = 0; j < 4; ++j) cols[j] = (j < nn) ? nc[j] : 0;
            }
        }
    }
    // make pair-mate's post-barrier sign writes visible before projection
    asm volatile("bar.sync %0, 64;" :: "r"(1 + pair) : "memory");

    // ================= projection: warp handles 2 of its pair's columns =================
    const float* hf = (cur == 0) ? Hb0 : Hb1;
    {
        int c0 = 4 * pair + 2 * half, c1 = c0 + 1;
        const float4 h0q = *(const float4*)(hf + c0 * HD + 4 * lane);
        const float4 h1q = *(const float4*)(hf + c1 * HD + 4 * lane);
        #pragma unroll
        for (int cls = 0; cls < CD; ++cls) {
            const float4 wq = __ldg((const float4*)(Wph + cls * HD) + lane);
            float s0 = h0q.x * wq.x + h0q.y * wq.y + h0q.z * wq.z + h0q.w * wq.w;
            float s1 = h1q.x * wq.x + h1q.y * wq.y + h1q.z * wq.z + h1q.w * wq.w;
            #pragma unroll
            for (int o = 16; o > 0; o >>= 1) {
                s0 += __shfl_xor_sync(0xffffffffu, s0, o);
                s1 += __shfl_xor_sync(0xffffffffu, s1, o);
            }
            if (lane == 0) {
                float bpv = __ldg(bp + cls);
                out[(size_t)(b0 + c0) * CD + cls] = s0 + bpv;
                out[(size_t)(b0 + c1) * CD + cls] = s1 + bpv;
            }
        }
    }
}

extern "C" void kernel_launch(void* const* d_in, const int* in_sizes, int n_in,
                              void* d_out, int out_size) {
    const float* x   = (const float*)d_in[0];
    const float* Whx = (const float*)d_in[1];
    const float* Whh = (const float*)d_in[2];
    const float* Wph = (const float*)d_in[3];
    const float* bh  = (const float*)d_in[4];
    const float* bp  = (const float*)d_in[5];
    cudaFuncSetAttribute(rnn_kernel, cudaFuncAttributeMaxDynamicSharedMemorySize, SM_SZ);
    rnn_kernel<<<NCTA, NTHR, SM_SZ>>>(x, Whx, Whh, Wph, bh, bp, (float*)d_out);
}